// round 5
// baseline (speedup 1.0000x reference)
#include <cuda_runtime.h>
#include <cstdint>

// Problem constants (n=1, C=256, t=8, h=64, w=64, heads=8)
#define HEADS 8
#define TT 8
#define HH 64
#define WW 64
#define SDIM (TT + HH + WW - 2)   // 134
#define SP (TT * HH * WW)          // 32768
#define PLANE (HH * WW)            // 4096
#define CDIM 256
#define CG (CDIM / HEADS)          // 32 channels per head

// Scratch for pv = conv(value)
__device__ float g_pv[CDIM * SP];

using ull = unsigned long long;

__device__ __forceinline__ ull packf2(float lo, float hi) {
    ull r;
    asm("mov.b64 %0, {%1, %2};" : "=l"(r) : "f"(lo), "f"(hi));
    return r;
}
__device__ __forceinline__ void unpackf2(ull v, float& lo, float& hi) {
    asm("mov.b64 {%0, %1}, %2;" : "=f"(lo), "=f"(hi) : "l"(v));
}
__device__ __forceinline__ void ffma2(ull& d, ull a, ull b) {
    asm("fma.rn.f32x2 %0, %1, %2, %3;" : "=l"(d) : "l"(a), "l"(b), "l"(d));
}

// ---------------------------------------------------------------------------
// Kernel 1: pv[o, s] = bias[o] + sum_c W[o, c] * V[c, s]   (R3 version)
// ---------------------------------------------------------------------------
__global__ void __launch_bounds__(256) conv_gemm_kernel(
    const float* __restrict__ V, const float* __restrict__ Wm,
    const float* __restrict__ bias)
{
    __shared__ float2 Ws2[16][32];  // [k][o], duplicated
    __shared__ float Vs[16][256];   // [k][s]

    const int tid = threadIdx.x;
    const int tx = tid & 31;
    const int ty = tid >> 5;
    const int oBase = blockIdx.y * 32;
    const int sBase = blockIdx.x * 256;

    ull acc[4][4];
    #pragma unroll
    for (int i = 0; i < 4; ++i) {
        float bv = bias[oBase + ty * 4 + i];
        ull pb = packf2(bv, bv);
        #pragma unroll
        for (int j = 0; j < 4; ++j) acc[i][j] = pb;
    }

    float4 wv;
    float4 vv[4];
    const int oo = tid >> 2;
    const int kb = (tid & 3) * 4;

    if (tid < 128) wv = *(const float4*)&Wm[(oBase + oo) * CDIM + 0 + kb];
    #pragma unroll
    for (int j = 0; j < 4; ++j) {
        int idx = tid + j * 256;
        int r = idx >> 6, c4 = idx & 63;
        vv[j] = *(const float4*)&V[(0 + r) * SP + sBase + c4 * 4];
    }

    for (int kk = 0; kk < CDIM; kk += 16) {
        __syncthreads();
        if (tid < 128) {
            Ws2[kb + 0][oo] = make_float2(wv.x, wv.x);
            Ws2[kb + 1][oo] = make_float2(wv.y, wv.y);
            Ws2[kb + 2][oo] = make_float2(wv.z, wv.z);
            Ws2[kb + 3][oo] = make_float2(wv.w, wv.w);
        }
        #pragma unroll
        for (int j = 0; j < 4; ++j) {
            int idx = tid + j * 256;
            int r = idx >> 6, c4 = idx & 63;
            *(float4*)&Vs[r][c4 * 4] = vv[j];
        }
        __syncthreads();

        int kn = kk + 16;
        if (kn < CDIM) {
            if (tid < 128) wv = *(const float4*)&Wm[(oBase + oo) * CDIM + kn + kb];
            #pragma unroll
            for (int j = 0; j < 4; ++j) {
                int idx = tid + j * 256;
                int r = idx >> 6, c4 = idx & 63;
                vv[j] = *(const float4*)&V[(kn + r) * SP + sBase + c4 * 4];
            }
        }

        #pragma unroll
        for (int k = 0; k < 16; ++k) {
            float4 b0 = *(const float4*)&Vs[k][tx * 4];
            float4 b1 = *(const float4*)&Vs[k][128 + tx * 4];
            ull bb0 = packf2(b0.x, b0.y);
            ull bb1 = packf2(b0.z, b0.w);
            ull bb2 = packf2(b1.x, b1.y);
            ull bb3 = packf2(b1.z, b1.w);
            #pragma unroll
            for (int i = 0; i < 4; ++i) {
                ull a2 = *reinterpret_cast<const ull*>(&Ws2[k][ty * 4 + i]);
                ffma2(acc[i][0], a2, bb0);
                ffma2(acc[i][1], a2, bb1);
                ffma2(acc[i][2], a2, bb2);
                ffma2(acc[i][3], a2, bb3);
            }
        }
    }

    #pragma unroll
    for (int i = 0; i < 4; ++i) {
        float r0, r1, r2, r3, r4, r5, r6, r7;
        unpackf2(acc[i][0], r0, r1);
        unpackf2(acc[i][1], r2, r3);
        unpackf2(acc[i][2], r4, r5);
        unpackf2(acc[i][3], r6, r7);
        float* dst = &g_pv[(oBase + ty * 4 + i) * SP + sBase];
        float4 v0 = {r0, r1, r2, r3};
        float4 v1 = {r4, r5, r6, r7};
        *(float4*)&dst[tx * 4] = v0;
        *(float4*)&dst[128 + tx * 4] = v1;
    }
}

// ---------------------------------------------------------------------------
// Kernel 2: t-sum (R3 version). 512 threads, pos-chunk 128.
// ---------------------------------------------------------------------------
__global__ void __launch_bounds__(512) attn_t_kernel(
    const float* __restrict__ A, float* __restrict__ out)
{
    __shared__ float ats[8 * 8 * 128];

    const int tid = threadIdx.x;
    const int pos = tid & 127;
    const int cg = tid >> 7;
    const int pos0 = blockIdx.x * 128;
    const int b = blockIdx.y;
    const int cbase = b * CG;
    const int attb = b * SDIM * SP;

    for (int i = tid; i < 8192; i += 512) {
        int p_i = i & 127, tau_i = (i >> 7) & 7, s_i = i >> 10;
        ats[i] = A[attb + s_i * SP + tau_i * PLANE + pos0 + p_i];
    }

    ull pvr[8][4];
    #pragma unroll
    for (int s = 0; s < 8; ++s)
        #pragma unroll
        for (int cp = 0; cp < 4; ++cp) {
            const float* g = &g_pv[(cbase + cg * 8 + 2 * cp) * SP + s * PLANE + pos0 + pos];
            pvr[s][cp] = packf2(g[0], g[SP]);
        }
    __syncthreads();

    ull z = packf2(0.0f, 0.0f);
    #pragma unroll 1
    for (int tau = 0; tau < 8; ++tau) {
        ull acc[4] = {z, z, z, z};
        #pragma unroll
        for (int s = 0; s < 8; ++s) {
            float at = ats[(s * 8 + tau) * 128 + pos];
            ull a2 = packf2(at, at);
            #pragma unroll
            for (int cp = 0; cp < 4; ++cp)
                ffma2(acc[cp], a2, pvr[s][cp]);
        }
        #pragma unroll
        for (int cp = 0; cp < 4; ++cp) {
            float lo, hi;
            unpackf2(acc[cp], lo, hi);
            float* o = &out[(cbase + cg * 8 + 2 * cp) * SP + tau * PLANE + pos0 + pos];
            o[0] = lo;
            o[SP] = hi;
        }
    }
}

// ---------------------------------------------------------------------------
// Kernel 3: h-sum, RMW. Occupancy redesign: x-tile 8, 1 channel-pair/thread.
// Block: (x-tile 8, tau, head) -> grid (8, 8, 8). 512 threads, 2 CTAs/SM.
// Thread: xq=tid&1 (x=4xq+k), qg=(tid>>1)&15 (q=4qg+qi), cg=tid>>5 (channels 2cg,2cg+1)
// smem: pvh2[64p][16cp2][8x] float2 = 64KB
// ---------------------------------------------------------------------------
__global__ void __launch_bounds__(512, 2) attn_h_kernel(
    const float* __restrict__ A, float* __restrict__ out)
{
    extern __shared__ float2 pvh2[];   // [p][cp2][8x]

    const int tid = threadIdx.x;
    const int xq = tid & 1;
    const int qg = (tid >> 1) & 15;
    const int cg = tid >> 5;            // 0..15, one cp2
    const int x0 = blockIdx.x * 8;
    const int tau = blockIdx.y;
    const int b = blockIdx.z;
    const int cbase = b * CG;
    const int attb = b * SDIM * SP;

    // load pv: [p][cp2][x]
    for (int i = tid; i < 8192; i += 512) {
        int x = i & 7, cp2 = (i >> 3) & 15, p = i >> 7;
        const float* g = &g_pv[(cbase + 2 * cp2) * SP + tau * PLANE + p * 64 + x0 + x];
        pvh2[(p * 16 + cp2) * 8 + x] = make_float2(g[0], g[SP]);
    }
    __syncthreads();

    ull z = packf2(0.0f, 0.0f);
    ull acc[4][4];   // [qi][k]
    #pragma unroll
    for (int qi = 0; qi < 4; ++qi)
        #pragma unroll
        for (int k = 0; k < 4; ++k) acc[qi][k] = z;

    const float* Ahb = A + attb + TT * SP + tau * PLANE;
    int qv[4];
    const float* pA[4];
    #pragma unroll
    for (int qi = 0; qi < 4; ++qi) {
        qv[qi] = 4 * qg + qi;
        pA[qi] = Ahb + qv[qi] * 64 + x0 + 4 * xq;   // j=0 row
    }

    #pragma unroll 2
    for (int p = 0; p < 64; ++p) {
        float4 av[4];
        #pragma unroll
        for (int qi = 0; qi < 4; ++qi)
            av[qi] = __ldg((const float4*)pA[qi]);
        #pragma unroll
        for (int qi = 0; qi < 4; ++qi)
            pA[qi] += (p != qv[qi]) ? SP : 0;

        ull pp[4];
        #pragma unroll
        for (int k = 0; k < 4; ++k)
            pp[k] = *reinterpret_cast<const ull*>(&pvh2[(p * 16 + cg) * 8 + 4 * xq + k]);

        #pragma unroll
        for (int qi = 0; qi < 4; ++qi) {
            float a0 = av[qi].x, a1 = av[qi].y, a2v = av[qi].z, a3 = av[qi].w;
            ffma2(acc[qi][0], packf2(a0, a0), pp[0]);
            ffma2(acc[qi][1], packf2(a1, a1), pp[1]);
            ffma2(acc[qi][2], packf2(a2v, a2v), pp[2]);
            ffma2(acc[qi][3], packf2(a3, a3), pp[3]);
        }
    }

    // subtract the bogus p==q term
    #pragma unroll
    for (int qi = 0; qi < 4; ++qi) {
        int q = qv[qi];
        float4 bv = __ldg((const float4*)&Ahb[q * SP + q * 64 + x0 + 4 * xq]);
        float bs[4] = {bv.x, bv.y, bv.z, bv.w};
        #pragma unroll
        for (int k = 0; k < 4; ++k) {
            ull nb = packf2(-bs[k], -bs[k]);
            ull p0 = *reinterpret_cast<const ull*>(&pvh2[(q * 16 + cg) * 8 + 4 * xq + k]);
            ffma2(acc[qi][k], nb, p0);
        }
    }

    // RMW store: per qi, two float4 (one per channel of the pair)
    #pragma unroll
    for (int qi = 0; qi < 4; ++qi) {
        int q = qv[qi];
        float lo[4], hi[4];
        #pragma unroll
        for (int k = 0; k < 4; ++k) unpackf2(acc[qi][k], lo[k], hi[k]);
        float* o0 = &out[(cbase + 2 * cg) * SP + tau * PLANE + q * 64 + x0 + 4 * xq];
        float* o1 = o0 + SP;
        float4 t0 = *(float4*)o0;
        float4 t1 = *(float4*)o1;
        t0.x += lo[0]; t0.y += lo[1]; t0.z += lo[2]; t0.w += lo[3];
        t1.x += hi[0]; t1.y += hi[1]; t1.z += hi[2]; t1.w += hi[3];
        *(float4*)o0 = t0;
        *(float4*)o1 = t1;
    }
}

// ---------------------------------------------------------------------------
// Kernel 4: w-sum, RMW. Occupancy redesign: q-tile 8, 2 channel-pairs/thread.
// Block: (q-tile 8, tau, head) -> grid (8, 8, 8). 512 threads, 2 CTAs/SM.
// Thread: xo=tid&7 (x=8xo+m), cg=(tid>>3)&7 (channels 4cg..4cg+3), qloc=tid>>6
// smem: pvw2[8q][64p][18cp2pad] float2 = 72KB
// ---------------------------------------------------------------------------
__global__ void __launch_bounds__(512, 2) attn_w_kernel(
    const float* __restrict__ A, float* __restrict__ out)
{
    extern __shared__ float2 pvw2[];   // [q][p][18]

    const int tid = threadIdx.x;
    const int xo = tid & 7;
    const int cg = (tid >> 3) & 7;
    const int qloc = tid >> 6;          // 0..7
    const int q0 = blockIdx.x * 8;
    const int tau = blockIdx.y;
    const int b = blockIdx.z;
    const int cbase = b * CG;
    const int attb = b * SDIM * SP;
    const int q = q0 + qloc;

    // load pv: [q][p][18cp2]
    for (int i = tid; i < 8192; i += 512) {
        int p = i & 63, qi = (i >> 6) & 7, cp2 = i >> 9;
        const float* g = &g_pv[(cbase + 2 * cp2) * SP + tau * PLANE + (q0 + qi) * 64 + p];
        pvw2[(qi * 64 + p) * 18 + cp2] = make_float2(g[0], g[SP]);
    }
    __syncthreads();

    ull z = packf2(0.0f, 0.0f);
    ull acc[8][2];     // [m][cp]  channels (4cg+2cp, 4cg+2cp+1)
    #pragma unroll
    for (int m = 0; m < 8; ++m) { acc[m][0] = z; acc[m][1] = z; }

    const float* Awb = A + attb + (TT + HH - 1) * SP + tau * PLANE + q * 64;
    const float* pA = Awb + 8 * xo;
    const int thr = 8 * xo + 7;

    #pragma unroll 4
    for (int j = 0; j < 63; ++j) {
        float4 av0 = __ldg((const float4*)pA);
        float4 av1 = __ldg((const float4*)(pA + 4));
        pA += SP;
        int p = j + (j >= thr ? 1 : 0);

        const ull* u = reinterpret_cast<const ull*>(&pvw2[(qloc * 64 + p) * 18 + 2 * cg]);
        ull pp0 = u[0], pp1 = u[1];

        float a[8] = {av0.x, av0.y, av0.z, av0.w, av1.x, av1.y, av1.z, av1.w};
        #pragma unroll
        for (int m = 0; m < 8; ++m) {
            ull am = packf2(a[m], a[m]);
            ffma2(acc[m][0], am, pp0);
            ffma2(acc[m][1], am, pp1);
        }
    }

    // corrections: for j = 8xo+jj (jj 0..6), lanes m <= jj used pv[j] but need pv[j+1]
    #pragma unroll 1
    for (int jj = 0; jj < 7; ++jj) {
        int j = 8 * xo + jj;
        const ull* uj  = reinterpret_cast<const ull*>(&pvw2[(qloc * 64 + j) * 18 + 2 * cg]);
        const ull* uj1 = reinterpret_cast<const ull*>(&pvw2[(qloc * 64 + j + 1) * 18 + 2 * cg]);
        ull pj0 = uj[0], pj1 = uj[1];
        ull q0_ = uj1[0], q1_ = uj1[1];
        for (int m = 0; m <= jj; ++m) {
            float bb = __ldg(&Awb[j * SP + 8 * xo + m]);
            ull b2 = packf2(bb, bb);
            ull nb2 = packf2(-bb, -bb);
            ffma2(acc[m][0], b2, q0_); ffma2(acc[m][0], nb2, pj0);
            ffma2(acc[m][1], b2, q1_); ffma2(acc[m][1], nb2, pj1);
        }
    }

    // RMW store
    #pragma unroll
    for (int cp = 0; cp < 2; ++cp) {
        float lo[8], hi[8];
        #pragma unroll
        for (int m = 0; m < 8; ++m) unpackf2(acc[m][cp], lo[m], hi[m]);
        float* o0 = &out[(cbase + 4 * cg + 2 * cp) * SP + tau * PLANE + q * 64 + 8 * xo];
        float* o1 = o0 + SP;
        float4 a0 = *(float4*)o0;          float4 a1 = *(float4*)(o0 + 4);
        float4 b0v = *(float4*)o1;         float4 b1v = *(float4*)(o1 + 4);
        a0.x += lo[0]; a0.y += lo[1]; a0.z += lo[2]; a0.w += lo[3];
        a1.x += lo[4]; a1.y += lo[5]; a1.z += lo[6]; a1.w += lo[7];
        b0v.x += hi[0]; b0v.y += hi[1]; b0v.z += hi[2]; b0v.w += hi[3];
        b1v.x += hi[4]; b1v.y += hi[5]; b1v.z += hi[6]; b1v.w += hi[7];
        *(float4*)o0 = a0;       *(float4*)(o0 + 4) = a1;
        *(float4*)o1 = b0v;      *(float4*)(o1 + 4) = b1v;
    }
}

// ---------------------------------------------------------------------------

extern "C" void kernel_launch(void* const* d_in, const int* in_sizes, int n_in,
                              void* d_out, int out_size) {
    (void)in_sizes; (void)n_in; (void)out_size;
    const float* A    = (const float*)d_in[0];
    const float* V    = (const float*)d_in[1];
    const float* Wm   = (const float*)d_in[2];
    const float* bias = (const float*)d_in[3];
    float* out = (float*)d_out;

    const int SMEM_H = 64 * 16 * 8 * (int)sizeof(float2);    // 65536
    const int SMEM_W = 8 * 64 * 18 * (int)sizeof(float2);    // 73728

    cudaFuncSetAttribute(attn_h_kernel, cudaFuncAttributeMaxDynamicSharedMemorySize, SMEM_H);
    cudaFuncSetAttribute(attn_w_kernel, cudaFuncAttributeMaxDynamicSharedMemorySize, SMEM_W);

    conv_gemm_kernel<<<dim3(SP / 256, CDIM / 32), 256>>>(V, Wm, bias);
    attn_t_kernel<<<dim3(PLANE / 128, HEADS), 512>>>(A, out);
    attn_h_kernel<<<dim3(8, TT, HEADS), 512, SMEM_H>>>(A, out);
    attn_w_kernel<<<dim3(8, TT, HEADS), 512, SMEM_W>>>(A, out);
}

// round 6
// speedup vs baseline: 1.5930x; 1.5930x over previous
#include <cuda_runtime.h>
#include <cstdint>

// Problem constants (n=1, C=256, t=8, h=64, w=64, heads=8)
#define HEADS 8
#define TT 8
#define HH 64
#define WW 64
#define SDIM (TT + HH + WW - 2)   // 134
#define SP (TT * HH * WW)          // 32768
#define PLANE (HH * WW)            // 4096
#define CDIM 256
#define CG (CDIM / HEADS)          // 32 channels per head

// Scratch for pv = conv(value)
__device__ float g_pv[CDIM * SP];

using ull = unsigned long long;

__device__ __forceinline__ ull packf2(float lo, float hi) {
    ull r;
    asm("mov.b64 %0, {%1, %2};" : "=l"(r) : "f"(lo), "f"(hi));
    return r;
}
__device__ __forceinline__ void unpackf2(ull v, float& lo, float& hi) {
    asm("mov.b64 {%0, %1}, %2;" : "=f"(lo), "=f"(hi) : "l"(v));
}
__device__ __forceinline__ void ffma2(ull& d, ull a, ull b) {
    asm("fma.rn.f32x2 %0, %1, %2, %3;" : "=l"(d) : "l"(a), "l"(b), "l"(d));
}
__device__ __forceinline__ uint32_t smem_u32(const void* p) {
    uint32_t a;
    asm("{ .reg .u64 t; cvta.to.shared.u64 t, %1; cvt.u32.u64 %0, t; }" : "=r"(a) : "l"(p));
    return a;
}
__device__ __forceinline__ void cp_async16(uint32_t dst, const void* src) {
    asm volatile("cp.async.ca.shared.global [%0], [%1], 16;" :: "r"(dst), "l"(src));
}
__device__ __forceinline__ void cp_commit() {
    asm volatile("cp.async.commit_group;");
}
template<int N>
__device__ __forceinline__ void cp_wait() {
    asm volatile("cp.async.wait_group %0;" :: "n"(N));
}

// ---------------------------------------------------------------------------
// Kernel 1: pv[o, s] = bias[o] + sum_c W[o, c] * V[c, s]   (R3 version)
// ---------------------------------------------------------------------------
__global__ void __launch_bounds__(256) conv_gemm_kernel(
    const float* __restrict__ V, const float* __restrict__ Wm,
    const float* __restrict__ bias)
{
    __shared__ float2 Ws2[16][32];
    __shared__ float Vs[16][256];

    const int tid = threadIdx.x;
    const int tx = tid & 31;
    const int ty = tid >> 5;
    const int oBase = blockIdx.y * 32;
    const int sBase = blockIdx.x * 256;

    ull acc[4][4];
    #pragma unroll
    for (int i = 0; i < 4; ++i) {
        float bv = bias[oBase + ty * 4 + i];
        ull pb = packf2(bv, bv);
        #pragma unroll
        for (int j = 0; j < 4; ++j) acc[i][j] = pb;
    }

    float4 wv;
    float4 vv[4];
    const int oo = tid >> 2;
    const int kb = (tid & 3) * 4;

    if (tid < 128) wv = *(const float4*)&Wm[(oBase + oo) * CDIM + 0 + kb];
    #pragma unroll
    for (int j = 0; j < 4; ++j) {
        int idx = tid + j * 256;
        int r = idx >> 6, c4 = idx & 63;
        vv[j] = *(const float4*)&V[(0 + r) * SP + sBase + c4 * 4];
    }

    for (int kk = 0; kk < CDIM; kk += 16) {
        __syncthreads();
        if (tid < 128) {
            Ws2[kb + 0][oo] = make_float2(wv.x, wv.x);
            Ws2[kb + 1][oo] = make_float2(wv.y, wv.y);
            Ws2[kb + 2][oo] = make_float2(wv.z, wv.z);
            Ws2[kb + 3][oo] = make_float2(wv.w, wv.w);
        }
        #pragma unroll
        for (int j = 0; j < 4; ++j) {
            int idx = tid + j * 256;
            int r = idx >> 6, c4 = idx & 63;
            *(float4*)&Vs[r][c4 * 4] = vv[j];
        }
        __syncthreads();

        int kn = kk + 16;
        if (kn < CDIM) {
            if (tid < 128) wv = *(const float4*)&Wm[(oBase + oo) * CDIM + kn + kb];
            #pragma unroll
            for (int j = 0; j < 4; ++j) {
                int idx = tid + j * 256;
                int r = idx >> 6, c4 = idx & 63;
                vv[j] = *(const float4*)&V[(kn + r) * SP + sBase + c4 * 4];
            }
        }

        #pragma unroll
        for (int k = 0; k < 16; ++k) {
            float4 b0 = *(const float4*)&Vs[k][tx * 4];
            float4 b1 = *(const float4*)&Vs[k][128 + tx * 4];
            ull bb0 = packf2(b0.x, b0.y);
            ull bb1 = packf2(b0.z, b0.w);
            ull bb2 = packf2(b1.x, b1.y);
            ull bb3 = packf2(b1.z, b1.w);
            #pragma unroll
            for (int i = 0; i < 4; ++i) {
                ull a2 = *reinterpret_cast<const ull*>(&Ws2[k][ty * 4 + i]);
                ffma2(acc[i][0], a2, bb0);
                ffma2(acc[i][1], a2, bb1);
                ffma2(acc[i][2], a2, bb2);
                ffma2(acc[i][3], a2, bb3);
            }
        }
    }

    #pragma unroll
    for (int i = 0; i < 4; ++i) {
        float r0, r1, r2, r3, r4, r5, r6, r7;
        unpackf2(acc[i][0], r0, r1);
        unpackf2(acc[i][1], r2, r3);
        unpackf2(acc[i][2], r4, r5);
        unpackf2(acc[i][3], r6, r7);
        float* dst = &g_pv[(oBase + ty * 4 + i) * SP + sBase];
        float4 v0 = {r0, r1, r2, r3};
        float4 v1 = {r4, r5, r6, r7};
        *(float4*)&dst[tx * 4] = v0;
        *(float4*)&dst[128 + tx * 4] = v1;
    }
}

// ---------------------------------------------------------------------------
// Kernel 2: t-sum (R3 version). 512 threads, pos-chunk 128.
// ---------------------------------------------------------------------------
__global__ void __launch_bounds__(512) attn_t_kernel(
    const float* __restrict__ A, float* __restrict__ out)
{
    __shared__ float ats[8 * 8 * 128];

    const int tid = threadIdx.x;
    const int pos = tid & 127;
    const int cg = tid >> 7;
    const int pos0 = blockIdx.x * 128;
    const int b = blockIdx.y;
    const int cbase = b * CG;
    const int attb = b * SDIM * SP;

    for (int i = tid; i < 8192; i += 512) {
        int p_i = i & 127, tau_i = (i >> 7) & 7, s_i = i >> 10;
        ats[i] = A[attb + s_i * SP + tau_i * PLANE + pos0 + p_i];
    }

    ull pvr[8][4];
    #pragma unroll
    for (int s = 0; s < 8; ++s)
        #pragma unroll
        for (int cp = 0; cp < 4; ++cp) {
            const float* g = &g_pv[(cbase + cg * 8 + 2 * cp) * SP + s * PLANE + pos0 + pos];
            pvr[s][cp] = packf2(g[0], g[SP]);
        }
    __syncthreads();

    ull z = packf2(0.0f, 0.0f);
    #pragma unroll 1
    for (int tau = 0; tau < 8; ++tau) {
        ull acc[4] = {z, z, z, z};
        #pragma unroll
        for (int s = 0; s < 8; ++s) {
            float at = ats[(s * 8 + tau) * 128 + pos];
            ull a2 = packf2(at, at);
            #pragma unroll
            for (int cp = 0; cp < 4; ++cp)
                ffma2(acc[cp], a2, pvr[s][cp]);
        }
        #pragma unroll
        for (int cp = 0; cp < 4; ++cp) {
            float lo, hi;
            unpackf2(acc[cp], lo, hi);
            float* o = &out[(cbase + cg * 8 + 2 * cp) * SP + tau * PLANE + pos0 + pos];
            o[0] = lo;
            o[SP] = hi;
        }
    }
}

// ---------------------------------------------------------------------------
// Kernel 3: h-sum, RMW. p-space (pv shared across qi), A rows staged via
// cp.async double buffer: chunk c stages rows (8c-1 .. 8c+7) clamped, q-rows
// padded to 20 floats. Thread map (R3): xq=tid&3, qg=(tid>>2)&15, cg=tid>>6.
// smem: pvh2[64p][16cp2][16x] float2 (128KB) + Ah_s[2][9][64][20] (92160B)
// ---------------------------------------------------------------------------
#define AH_BUF (9 * 64 * 20)   // 11520 floats per buffer

__global__ void __launch_bounds__(512) attn_h_kernel(
    const float* __restrict__ A, float* __restrict__ out)
{
    extern __shared__ float smemh[];
    float2* pvh2 = (float2*)smemh;            // 64*16*16 float2 = 32768 floats
    float* Ah_s = smemh + 32768;              // [2][AH_BUF]

    const int tid = threadIdx.x;
    const int xq = tid & 3;
    const int qg = (tid >> 2) & 15;
    const int cg = tid >> 6;            // 0..7 (channels 4cg..4cg+3 = cp2 {2cg, 2cg+1})
    const int x0 = blockIdx.x * 16;
    const int tau = blockIdx.y;
    const int b = blockIdx.z;
    const int cbase = b * CG;
    const int attb = b * SDIM * SP;

    const float* Ahb = A + attb + TT * SP + tau * PLANE;   // + j*SP + q*64 + x
    const uint32_t As_u32 = smem_u32(Ah_s);

    // pv load: [p][cp2][x]
    for (int i = tid; i < 16384; i += 512) {
        int x = i & 15, p = (i >> 4) & 63, cp2 = i >> 10;
        const float* g = &g_pv[(cbase + 2 * cp2) * SP + tau * PLANE + p * 64 + x0 + x];
        pvh2[(p * 16 + cp2) * 16 + x] = make_float2(g[0], g[SP]);
    }

    // stage helper: chunk c -> buffer buf. rows r=0..8 hold A_h row (8c-1+r) clamped.
    auto stage = [&](int c, int buf) {
        #pragma unroll
        for (int k = 0; k < 5; ++k) {
            int idx = tid + 512 * k;
            if (idx < 2304) {
                int r = idx >> 8, rem = idx & 255;
                int qq = rem >> 2, x4 = rem & 3;
                int jrow = 8 * c - 1 + r;
                jrow = jrow < 0 ? 0 : (jrow > 63 ? 63 : jrow);
                const float* src = Ahb + jrow * SP + qq * 64 + x0 + x4 * 4;
                uint32_t dst = As_u32 + (buf * AH_BUF + (r * 64 + qq) * 20 + x4 * 4) * 4;
                cp_async16(dst, src);
            }
        }
    };

    stage(0, 0);
    cp_commit();

    ull z = packf2(0.0f, 0.0f);
    ull acc[4][4][2];   // [qi][k][r2]
    #pragma unroll
    for (int qi = 0; qi < 4; ++qi)
        #pragma unroll
        for (int k = 0; k < 4; ++k) { acc[qi][k][0] = z; acc[qi][k][1] = z; }

    int qv[4];
    #pragma unroll
    for (int qi = 0; qi < 4; ++qi) qv[qi] = 4 * qg + qi;

    #pragma unroll 1
    for (int c = 0; c < 8; ++c) {
        if (c < 7) { stage(c + 1, (c + 1) & 1); cp_commit(); }
        if (c < 7) cp_wait<1>(); else cp_wait<0>();
        __syncthreads();

        const float* Ab = Ah_s + (c & 1) * AH_BUF;

        #pragma unroll
        for (int pp = 0; pp < 8; ++pp) {
            const int p = 8 * c + pp;
            const int loc = pp + 1;

            float4 av[4];
            #pragma unroll
            for (int qi = 0; qi < 4; ++qi) {
                int lr = loc - ((p > qv[qi]) ? 1 : 0);
                av[qi] = *(const float4*)&Ab[(lr * 64 + qv[qi]) * 20 + 4 * xq];
            }

            ull pw[4][2];
            #pragma unroll
            for (int k = 0; k < 4; ++k) {
                pw[k][0] = *reinterpret_cast<const ull*>(&pvh2[(p * 16 + 2 * cg + 0) * 16 + 4 * xq + k]);
                pw[k][1] = *reinterpret_cast<const ull*>(&pvh2[(p * 16 + 2 * cg + 1) * 16 + 4 * xq + k]);
            }
            #pragma unroll
            for (int qi = 0; qi < 4; ++qi) {
                float a0 = av[qi].x, a1 = av[qi].y, a2v = av[qi].z, a3 = av[qi].w;
                ull b0 = packf2(a0, a0), b1 = packf2(a1, a1);
                ull b2 = packf2(a2v, a2v), b3 = packf2(a3, a3);
                ffma2(acc[qi][0][0], b0, pw[0][0]); ffma2(acc[qi][0][1], b0, pw[0][1]);
                ffma2(acc[qi][1][0], b1, pw[1][0]); ffma2(acc[qi][1][1], b1, pw[1][1]);
                ffma2(acc[qi][2][0], b2, pw[2][0]); ffma2(acc[qi][2][1], b2, pw[2][1]);
                ffma2(acc[qi][3][0], b3, pw[3][0]); ffma2(acc[qi][3][1], b3, pw[3][1]);
            }
        }
        __syncthreads();
    }

    // subtract the bogus p==q term: A_h row j=q at (q, x) times pv[p=q]
    #pragma unroll
    for (int qi = 0; qi < 4; ++qi) {
        int q = qv[qi];
        float4 bv = __ldg((const float4*)&Ahb[q * SP + q * 64 + x0 + 4 * xq]);
        float bs[4] = {bv.x, bv.y, bv.z, bv.w};
        #pragma unroll
        for (int k = 0; k < 4; ++k) {
            ull nb = packf2(-bs[k], -bs[k]);
            ull p0 = *reinterpret_cast<const ull*>(&pvh2[(q * 16 + 2 * cg + 0) * 16 + 4 * xq + k]);
            ull p1 = *reinterpret_cast<const ull*>(&pvh2[(q * 16 + 2 * cg + 1) * 16 + 4 * xq + k]);
            ffma2(acc[qi][k][0], nb, p0);
            ffma2(acc[qi][k][1], nb, p1);
        }
    }

    // RMW store
    #pragma unroll
    for (int qi = 0; qi < 4; ++qi) {
        int q = qv[qi];
        #pragma unroll
        for (int r = 0; r < 2; ++r) {
            float lo[4], hi[4];
            #pragma unroll
            for (int k = 0; k < 4; ++k) unpackf2(acc[qi][k][r], lo[k], hi[k]);
            float* o0 = &out[(cbase + 4 * cg + 2 * r) * SP + tau * PLANE + q * 64 + x0 + 4 * xq];
            float* o1 = o0 + SP;
            float4 t0 = *(float4*)o0;
            float4 t1 = *(float4*)o1;
            t0.x += lo[0]; t0.y += lo[1]; t0.z += lo[2]; t0.w += lo[3];
            t1.x += hi[0]; t1.y += hi[1]; t1.z += hi[2]; t1.w += hi[3];
            *(float4*)o0 = t0;
            *(float4*)o1 = t1;
        }
    }
}

// ---------------------------------------------------------------------------
// Kernel 4: w-sum, RMW. j-space with cp.async double-buffered A staging
// (chunks of 8 rows). Thread map (R3): xo=tid&7, cg=(tid>>3)&3, qloc=tid>>5.
// smem: pvw2[16q][64p][18cp2] float2 (144KB) + Aw_s[2][8][16][64] (64KB)
// ---------------------------------------------------------------------------
#define AW_BUF (8 * 16 * 64)   // 8192 floats per buffer

__global__ void __launch_bounds__(512) attn_w_kernel(
    const float* __restrict__ A, float* __restrict__ out)
{
    extern __shared__ float smemw[];
    float2* pvw2 = (float2*)smemw;            // 16*64*18 float2 = 36864 floats
    float* Aw_s = smemw + 36864;              // [2][AW_BUF]

    const int tid = threadIdx.x;
    const int xo = tid & 7;
    const int cg = (tid >> 3) & 3;
    const int qloc = tid >> 5;          // 0..15
    const int q0 = blockIdx.x * 16;
    const int tau = blockIdx.y;
    const int b = blockIdx.z;
    const int cbase = b * CG;
    const int attb = b * SDIM * SP;
    const int q = q0 + qloc;

    const float* Awb_blk = A + attb + (TT + HH - 1) * SP + tau * PLANE;  // + j*SP + q*64 + x
    const float* Awb = Awb_blk + q * 64;
    const uint32_t As_u32 = smem_u32(Aw_s);

    // load pv: [q][p][18cp2]
    for (int i = tid; i < 16384; i += 512) {
        int p = i & 63, qi = (i >> 6) & 15, cp2 = i >> 10;
        const float* g = &g_pv[(cbase + 2 * cp2) * SP + tau * PLANE + (q0 + qi) * 64 + p];
        pvw2[(qi * 64 + p) * 18 + cp2] = make_float2(g[0], g[SP]);
    }

    // stage helper: chunk c (rows 8c..8c+7, clamped to 62) -> buffer buf
    auto stage = [&](int c, int buf) {
        #pragma unroll
        for (int k = 0; k < 4; ++k) {
            int idx = tid + 512 * k;     // 0..2047
            int row = idx >> 8, rem = idx & 255;
            int qq = rem >> 4, x4 = rem & 15;
            int j = 8 * c + row;
            if (j > 62) j = 62;
            const float* src = Awb_blk + j * SP + (q0 + qq) * 64 + x4 * 4;
            uint32_t dst = As_u32 + (buf * AW_BUF + (row * 16 + qq) * 64 + x4 * 4) * 4;
            cp_async16(dst, src);
        }
    };

    stage(0, 0);
    cp_commit();

    ull z = packf2(0.0f, 0.0f);
    ull acc[8][4];
    #pragma unroll
    for (int m = 0; m < 8; ++m)
        #pragma unroll
        for (int cp = 0; cp < 4; ++cp) acc[m][cp] = z;

    const int thr = 8 * xo + 7;

    #pragma unroll 1
    for (int c = 0; c < 8; ++c) {
        if (c < 7) { stage(c + 1, (c + 1) & 1); cp_commit(); }
        if (c < 7) cp_wait<1>(); else cp_wait<0>();
        __syncthreads();

        const float* Ab = Aw_s + (c & 1) * AW_BUF;
        const int jmax = (c < 7) ? 8 : 7;

        #pragma unroll
        for (int jj = 0; jj < 8; ++jj) {
            if (jj >= jmax) break;
            const int j = 8 * c + jj;
            const float* ap = &Ab[(jj * 16 + qloc) * 64 + 8 * xo];
            float4 av0 = *(const float4*)ap;
            float4 av1 = *(const float4*)(ap + 4);

            int p = j + (j >= thr ? 1 : 0);
            const ull* u = reinterpret_cast<const ull*>(&pvw2[(qloc * 64 + p) * 18 + 4 * cg]);
            ull pp0 = u[0], pp1 = u[1], pp2 = u[2], pp3 = u[3];

            float a[8] = {av0.x, av0.y, av0.z, av0.w, av1.x, av1.y, av1.z, av1.w};
            #pragma unroll
            for (int m = 0; m < 8; ++m) {
                ull am = packf2(a[m], a[m]);
                ffma2(acc[m][0], am, pp0);
                ffma2(acc[m][1], am, pp1);
                ffma2(acc[m][2], am, pp2);
                ffma2(acc[m][3], am, pp3);
            }
        }
        __syncthreads();
    }

    // corrections: for j = 8xo+jj (jj 0..6), lanes m <= jj used pv[j] but need pv[j+1]
    #pragma unroll 1
    for (int jj = 0; jj < 7; ++jj) {
        int j = 8 * xo + jj;
        const ull* uj  = reinterpret_cast<const ull*>(&pvw2[(qloc * 64 + j) * 18 + 4 * cg]);
        const ull* uj1 = reinterpret_cast<const ull*>(&pvw2[(qloc * 64 + j + 1) * 18 + 4 * cg]);
        ull pj0 = uj[0], pj1 = uj[1], pj2 = uj[2], pj3 = uj[3];
        ull q0_ = uj1[0], q1_ = uj1[1], q2_ = uj1[2], q3_ = uj1[3];
        for (int m = 0; m <= jj; ++m) {
            float bb = __ldg(&Awb[j * SP + 8 * xo + m]);
            ull b2 = packf2(bb, bb);
            ull nb2 = packf2(-bb, -bb);
            ffma2(acc[m][0], b2, q0_); ffma2(acc[m][0], nb2, pj0);
            ffma2(acc[m][1], b2, q1_); ffma2(acc[m][1], nb2, pj1);
            ffma2(acc[m][2], b2, q2_); ffma2(acc[m][2], nb2, pj2);
            ffma2(acc[m][3], b2, q3_); ffma2(acc[m][3], nb2, pj3);
        }
    }

    // RMW store
    #pragma unroll
    for (int cp = 0; cp < 4; ++cp) {
        float lo[8], hi[8];
        #pragma unroll
        for (int m = 0; m < 8; ++m) unpackf2(acc[m][cp], lo[m], hi[m]);
        float* o0 = &out[(cbase + 8 * cg + 2 * cp) * SP + tau * PLANE + q * 64 + 8 * xo];
        float* o1 = o0 + SP;
        float4 a0 = *(float4*)o0;          float4 a1 = *(float4*)(o0 + 4);
        float4 b0v = *(float4*)o1;         float4 b1v = *(float4*)(o1 + 4);
        a0.x += lo[0]; a0.y += lo[1]; a0.z += lo[2]; a0.w += lo[3];
        a1.x += lo[4]; a1.y += lo[5]; a1.z += lo[6]; a1.w += lo[7];
        b0v.x += hi[0]; b0v.y += hi[1]; b0v.z += hi[2]; b0v.w += hi[3];
        b1v.x += hi[4]; b1v.y += hi[5]; b1v.z += hi[6]; b1v.w += hi[7];
        *(float4*)o0 = a0;       *(float4*)(o0 + 4) = a1;
        *(float4*)o1 = b0v;      *(float4*)(o1 + 4) = b1v;
    }
}

// ---------------------------------------------------------------------------

extern "C" void kernel_launch(void* const* d_in, const int* in_sizes, int n_in,
                              void* d_out, int out_size) {
    (void)in_sizes; (void)n_in; (void)out_size;
    const float* A    = (const float*)d_in[0];
    const float* V    = (const float*)d_in[1];
    const float* Wm   = (const float*)d_in[2];
    const float* bias = (const float*)d_in[3];
    float* out = (float*)d_out;

    const int SMEM_H = 32768 * 4 + 2 * AH_BUF * 4;   // 131072 + 92160 = 223232
    const int SMEM_W = 36864 * 4 + 2 * AW_BUF * 4;   // 147456 + 65536 = 212992

    cudaFuncSetAttribute(attn_h_kernel, cudaFuncAttributeMaxDynamicSharedMemorySize, SMEM_H);
    cudaFuncSetAttribute(attn_w_kernel, cudaFuncAttributeMaxDynamicSharedMemorySize, SMEM_W);

    conv_gemm_kernel<<<dim3(SP / 256, CDIM / 32), 256>>>(V, Wm, bias);
    attn_t_kernel<<<dim3(PLANE / 128, HEADS), 512>>>(A, out);
    attn_h_kernel<<<dim3(4, TT, HEADS), 512, SMEM_H>>>(A, out);
    attn_w_kernel<<<dim3(4, TT, HEADS), 512, SMEM_W>>>(A, out);
}

// round 7
// speedup vs baseline: 1.6022x; 1.0058x over previous
#include <cuda_runtime.h>
#include <cstdint>

// Problem constants (n=1, C=256, t=8, h=64, w=64, heads=8)
#define HEADS 8
#define TT 8
#define HH 64
#define WW 64
#define SDIM (TT + HH + WW - 2)   // 134
#define SP (TT * HH * WW)          // 32768
#define PLANE (HH * WW)            // 4096
#define CDIM 256
#define CG (CDIM / HEADS)          // 32 channels per head

// Scratch for pv = conv(value)
__device__ float g_pv[CDIM * SP];

using ull = unsigned long long;

__device__ __forceinline__ ull packf2(float lo, float hi) {
    ull r;
    asm("mov.b64 %0, {%1, %2};" : "=l"(r) : "f"(lo), "f"(hi));
    return r;
}
__device__ __forceinline__ void unpackf2(ull v, float& lo, float& hi) {
    asm("mov.b64 {%0, %1}, %2;" : "=f"(lo), "=f"(hi) : "l"(v));
}
__device__ __forceinline__ void ffma2(ull& d, ull a, ull b) {
    asm("fma.rn.f32x2 %0, %1, %2, %3;" : "=l"(d) : "l"(a), "l"(b), "l"(d));
}
__device__ __forceinline__ uint32_t smem_u32(const void* p) {
    uint32_t a;
    asm("{ .reg .u64 t; cvta.to.shared.u64 t, %1; cvt.u32.u64 %0, t; }" : "=r"(a) : "l"(p));
    return a;
}
__device__ __forceinline__ void cp_async16(uint32_t dst, const void* src) {
    asm volatile("cp.async.ca.shared.global [%0], [%1], 16;" :: "r"(dst), "l"(src));
}
__device__ __forceinline__ void cp_commit() {
    asm volatile("cp.async.commit_group;");
}
template<int N>
__device__ __forceinline__ void cp_wait() {
    asm volatile("cp.async.wait_group %0;" :: "n"(N));
}

// ---------------------------------------------------------------------------
// Kernel 1: pv[o, s] = bias[o] + sum_c W[o, c] * V[c, s]   (R3 version)
// ---------------------------------------------------------------------------
__global__ void __launch_bounds__(256) conv_gemm_kernel(
    const float* __restrict__ V, const float* __restrict__ Wm,
    const float* __restrict__ bias)
{
    __shared__ float2 Ws2[16][32];
    __shared__ float Vs[16][256];

    const int tid = threadIdx.x;
    const int tx = tid & 31;
    const int ty = tid >> 5;
    const int oBase = blockIdx.y * 32;
    const int sBase = blockIdx.x * 256;

    ull acc[4][4];
    #pragma unroll
    for (int i = 0; i < 4; ++i) {
        float bv = bias[oBase + ty * 4 + i];
        ull pb = packf2(bv, bv);
        #pragma unroll
        for (int j = 0; j < 4; ++j) acc[i][j] = pb;
    }

    float4 wv;
    float4 vv[4];
    const int oo = tid >> 2;
    const int kb = (tid & 3) * 4;

    if (tid < 128) wv = *(const float4*)&Wm[(oBase + oo) * CDIM + 0 + kb];
    #pragma unroll
    for (int j = 0; j < 4; ++j) {
        int idx = tid + j * 256;
        int r = idx >> 6, c4 = idx & 63;
        vv[j] = *(const float4*)&V[(0 + r) * SP + sBase + c4 * 4];
    }

    for (int kk = 0; kk < CDIM; kk += 16) {
        __syncthreads();
        if (tid < 128) {
            Ws2[kb + 0][oo] = make_float2(wv.x, wv.x);
            Ws2[kb + 1][oo] = make_float2(wv.y, wv.y);
            Ws2[kb + 2][oo] = make_float2(wv.z, wv.z);
            Ws2[kb + 3][oo] = make_float2(wv.w, wv.w);
        }
        #pragma unroll
        for (int j = 0; j < 4; ++j) {
            int idx = tid + j * 256;
            int r = idx >> 6, c4 = idx & 63;
            *(float4*)&Vs[r][c4 * 4] = vv[j];
        }
        __syncthreads();

        int kn = kk + 16;
        if (kn < CDIM) {
            if (tid < 128) wv = *(const float4*)&Wm[(oBase + oo) * CDIM + kn + kb];
            #pragma unroll
            for (int j = 0; j < 4; ++j) {
                int idx = tid + j * 256;
                int r = idx >> 6, c4 = idx & 63;
                vv[j] = *(const float4*)&V[(kn + r) * SP + sBase + c4 * 4];
            }
        }

        #pragma unroll
        for (int k = 0; k < 16; ++k) {
            float4 b0 = *(const float4*)&Vs[k][tx * 4];
            float4 b1 = *(const float4*)&Vs[k][128 + tx * 4];
            ull bb0 = packf2(b0.x, b0.y);
            ull bb1 = packf2(b0.z, b0.w);
            ull bb2 = packf2(b1.x, b1.y);
            ull bb3 = packf2(b1.z, b1.w);
            #pragma unroll
            for (int i = 0; i < 4; ++i) {
                ull a2 = *reinterpret_cast<const ull*>(&Ws2[k][ty * 4 + i]);
                ffma2(acc[i][0], a2, bb0);
                ffma2(acc[i][1], a2, bb1);
                ffma2(acc[i][2], a2, bb2);
                ffma2(acc[i][3], a2, bb3);
            }
        }
    }

    #pragma unroll
    for (int i = 0; i < 4; ++i) {
        float r0, r1, r2, r3, r4, r5, r6, r7;
        unpackf2(acc[i][0], r0, r1);
        unpackf2(acc[i][1], r2, r3);
        unpackf2(acc[i][2], r4, r5);
        unpackf2(acc[i][3], r6, r7);
        float* dst = &g_pv[(oBase + ty * 4 + i) * SP + sBase];
        float4 v0 = {r0, r1, r2, r3};
        float4 v1 = {r4, r5, r6, r7};
        *(float4*)&dst[tx * 4] = v0;
        *(float4*)&dst[128 + tx * 4] = v1;
    }
}

// ---------------------------------------------------------------------------
// Kernel 2: t-sum (R3 version). 512 threads, pos-chunk 128.
// ---------------------------------------------------------------------------
__global__ void __launch_bounds__(512) attn_t_kernel(
    const float* __restrict__ A, float* __restrict__ out)
{
    __shared__ float ats[8 * 8 * 128];

    const int tid = threadIdx.x;
    const int pos = tid & 127;
    const int cg = tid >> 7;
    const int pos0 = blockIdx.x * 128;
    const int b = blockIdx.y;
    const int cbase = b * CG;
    const int attb = b * SDIM * SP;

    for (int i = tid; i < 8192; i += 512) {
        int p_i = i & 127, tau_i = (i >> 7) & 7, s_i = i >> 10;
        ats[i] = A[attb + s_i * SP + tau_i * PLANE + pos0 + p_i];
    }

    ull pvr[8][4];
    #pragma unroll
    for (int s = 0; s < 8; ++s)
        #pragma unroll
        for (int cp = 0; cp < 4; ++cp) {
            const float* g = &g_pv[(cbase + cg * 8 + 2 * cp) * SP + s * PLANE + pos0 + pos];
            pvr[s][cp] = packf2(g[0], g[SP]);
        }
    __syncthreads();

    ull z = packf2(0.0f, 0.0f);
    #pragma unroll 1
    for (int tau = 0; tau < 8; ++tau) {
        ull acc[4] = {z, z, z, z};
        #pragma unroll
        for (int s = 0; s < 8; ++s) {
            float at = ats[(s * 8 + tau) * 128 + pos];
            ull a2 = packf2(at, at);
            #pragma unroll
            for (int cp = 0; cp < 4; ++cp)
                ffma2(acc[cp], a2, pvr[s][cp]);
        }
        #pragma unroll
        for (int cp = 0; cp < 4; ++cp) {
            float lo, hi;
            unpackf2(acc[cp], lo, hi);
            float* o = &out[(cbase + cg * 8 + 2 * cp) * SP + tau * PLANE + pos0 + pos];
            o[0] = lo;
            o[SP] = hi;
        }
    }
}

// ---------------------------------------------------------------------------
// Kernel 3: h-sum, RMW. p-space (pv shared across qi), A rows staged via
// cp.async double buffer: chunk c stages rows (8c-1 .. 8c+7) clamped, q-rows
// padded to 20 floats. Thread map (R3): xq=tid&3, qg=(tid>>2)&15, cg=tid>>6.
// smem: pvh2[64p][16cp2][16x] float2 (128KB) + Ah_s[2][9][64][20] (92160B)
// ---------------------------------------------------------------------------
#define AH_BUF (9 * 64 * 20)   // 11520 floats per buffer

__global__ void __launch_bounds__(512) attn_h_kernel(
    const float* __restrict__ A, float* __restrict__ out)
{
    extern __shared__ float smemh[];
    float2* pvh2 = (float2*)smemh;            // 64*16*16 float2 = 32768 floats
    float* Ah_s = smemh + 32768;              // [2][AH_BUF]

    const int tid = threadIdx.x;
    const int xq = tid & 3;
    const int qg = (tid >> 2) & 15;
    const int cg = tid >> 6;            // 0..7 (channels 4cg..4cg+3 = cp2 {2cg, 2cg+1})
    const int x0 = blockIdx.x * 16;
    const int tau = blockIdx.y;
    const int b = blockIdx.z;
    const int cbase = b * CG;
    const int attb = b * SDIM * SP;

    const float* Ahb = A + attb + TT * SP + tau * PLANE;   // + j*SP + q*64 + x
    const uint32_t As_u32 = smem_u32(Ah_s);

    // pv load: [p][cp2][x]
    for (int i = tid; i < 16384; i += 512) {
        int x = i & 15, p = (i >> 4) & 63, cp2 = i >> 10;
        const float* g = &g_pv[(cbase + 2 * cp2) * SP + tau * PLANE + p * 64 + x0 + x];
        pvh2[(p * 16 + cp2) * 16 + x] = make_float2(g[0], g[SP]);
    }

    // stage helper: chunk c -> buffer buf. rows r=0..8 hold A_h row (8c-1+r) clamped.
    auto stage = [&](int c, int buf) {
        #pragma unroll
        for (int k = 0; k < 5; ++k) {
            int idx = tid + 512 * k;
            if (idx < 2304) {
                int r = idx >> 8, rem = idx & 255;
                int qq = rem >> 2, x4 = rem & 3;
                int jrow = 8 * c - 1 + r;
                jrow = jrow < 0 ? 0 : (jrow > 63 ? 63 : jrow);
                const float* src = Ahb + jrow * SP + qq * 64 + x0 + x4 * 4;
                uint32_t dst = As_u32 + (buf * AH_BUF + (r * 64 + qq) * 20 + x4 * 4) * 4;
                cp_async16(dst, src);
            }
        }
    };

    stage(0, 0);
    cp_commit();

    ull z = packf2(0.0f, 0.0f);
    ull acc[4][4][2];   // [qi][k][r2]
    #pragma unroll
    for (int qi = 0; qi < 4; ++qi)
        #pragma unroll
        for (int k = 0; k < 4; ++k) { acc[qi][k][0] = z; acc[qi][k][1] = z; }

    int qv[4];
    #pragma unroll
    for (int qi = 0; qi < 4; ++qi) qv[qi] = 4 * qg + qi;

    #pragma unroll 1
    for (int c = 0; c < 8; ++c) {
        if (c < 7) { stage(c + 1, (c + 1) & 1); cp_commit(); }
        if (c < 7) cp_wait<1>(); else cp_wait<0>();
        __syncthreads();

        const float* Ab = Ah_s + (c & 1) * AH_BUF;

        #pragma unroll
        for (int pp = 0; pp < 8; ++pp) {
            const int p = 8 * c + pp;
            const int loc = pp + 1;

            float4 av[4];
            #pragma unroll
            for (int qi = 0; qi < 4; ++qi) {
                int lr = loc - ((p > qv[qi]) ? 1 : 0);
                av[qi] = *(const float4*)&Ab[(lr * 64 + qv[qi]) * 20 + 4 * xq];
            }

            ull pw[4][2];
            #pragma unroll
            for (int k = 0; k < 4; ++k) {
                pw[k][0] = *reinterpret_cast<const ull*>(&pvh2[(p * 16 + 2 * cg + 0) * 16 + 4 * xq + k]);
                pw[k][1] = *reinterpret_cast<const ull*>(&pvh2[(p * 16 + 2 * cg + 1) * 16 + 4 * xq + k]);
            }
            #pragma unroll
            for (int qi = 0; qi < 4; ++qi) {
                float a0 = av[qi].x, a1 = av[qi].y, a2v = av[qi].z, a3 = av[qi].w;
                ull b0 = packf2(a0, a0), b1 = packf2(a1, a1);
                ull b2 = packf2(a2v, a2v), b3 = packf2(a3, a3);
                ffma2(acc[qi][0][0], b0, pw[0][0]); ffma2(acc[qi][0][1], b0, pw[0][1]);
                ffma2(acc[qi][1][0], b1, pw[1][0]); ffma2(acc[qi][1][1], b1, pw[1][1]);
                ffma2(acc[qi][2][0], b2, pw[2][0]); ffma2(acc[qi][2][1], b2, pw[2][1]);
                ffma2(acc[qi][3][0], b3, pw[3][0]); ffma2(acc[qi][3][1], b3, pw[3][1]);
            }
        }
        __syncthreads();
    }

    // subtract the bogus p==q term: A_h row j=q at (q, x) times pv[p=q]
    #pragma unroll
    for (int qi = 0; qi < 4; ++qi) {
        int q = qv[qi];
        float4 bv = __ldg((const float4*)&Ahb[q * SP + q * 64 + x0 + 4 * xq]);
        float bs[4] = {bv.x, bv.y, bv.z, bv.w};
        #pragma unroll
        for (int k = 0; k < 4; ++k) {
            ull nb = packf2(-bs[k], -bs[k]);
            ull p0 = *reinterpret_cast<const ull*>(&pvh2[(q * 16 + 2 * cg + 0) * 16 + 4 * xq + k]);
            ull p1 = *reinterpret_cast<const ull*>(&pvh2[(q * 16 + 2 * cg + 1) * 16 + 4 * xq + k]);
            ffma2(acc[qi][k][0], nb, p0);
            ffma2(acc[qi][k][1], nb, p1);
        }
    }

    // RMW store
    #pragma unroll
    for (int qi = 0; qi < 4; ++qi) {
        int q = qv[qi];
        #pragma unroll
        for (int r = 0; r < 2; ++r) {
            float lo[4], hi[4];
            #pragma unroll
            for (int k = 0; k < 4; ++k) unpackf2(acc[qi][k][r], lo[k], hi[k]);
            float* o0 = &out[(cbase + 4 * cg + 2 * r) * SP + tau * PLANE + q * 64 + x0 + 4 * xq];
            float* o1 = o0 + SP;
            float4 t0 = *(float4*)o0;
            float4 t1 = *(float4*)o1;
            t0.x += lo[0]; t0.y += lo[1]; t0.z += lo[2]; t0.w += lo[3];
            t1.x += hi[0]; t1.y += hi[1]; t1.z += hi[2]; t1.w += hi[3];
            *(float4*)o0 = t0;
            *(float4*)o1 = t1;
        }
    }
}

// ---------------------------------------------------------------------------
// Kernel 4: w-sum, RMW. j-space with cp.async double-buffered A staging
// (chunks of 8 rows). Thread map (R3): xo=tid&7, cg=(tid>>3)&3, qloc=tid>>5.
// smem: pvw2[16q][64p][18cp2] float2 (144KB) + Aw_s[2][8][16][64] (64KB)
// ---------------------------------------------------------------------------
#define AW_BUF (8 * 16 * 64)   // 8192 floats per buffer

__global__ void __launch_bounds__(512) attn_w_kernel(
    const float* __restrict__ A, float* __restrict__ out)
{
    extern __shared__ float smemw[];
    float2* pvw2 = (float2*)smemw;            // 16*64*18 float2 = 36864 floats
    float* Aw_s = smemw + 36864;              // [2][AW_BUF]

    const int tid = threadIdx.x;
    const int xo = tid & 7;
    const int cg = (tid >> 3) & 3;
    const int qloc = tid >> 5;          // 0..15
    const int q0 = blockIdx.x * 16;
    const int tau = blockIdx.y;
    const int b = blockIdx.z;
    const int cbase = b * CG;
    const int attb = b * SDIM * SP;
    const int q = q0 + qloc;

    const float* Awb_blk = A + attb + (TT + HH - 1) * SP + tau * PLANE;  // + j*SP + q*64 + x
    const float* Awb = Awb_blk + q * 64;
    const uint32_t As_u32 = smem_u32(Aw_s);

    // load pv: [q][p][18cp2]
    for (int i = tid; i < 16384; i += 512) {
        int p = i & 63, qi = (i >> 6) & 15, cp2 = i >> 10;
        const float* g = &g_pv[(cbase + 2 * cp2) * SP + tau * PLANE + (q0 + qi) * 64 + p];
        pvw2[(qi * 64 + p) * 18 + cp2] = make_float2(g[0], g[SP]);
    }

    // stage helper: chunk c (rows 8c..8c+7, clamped to 62) -> buffer buf
    auto stage = [&](int c, int buf) {
        #pragma unroll
        for (int k = 0; k < 4; ++k) {
            int idx = tid + 512 * k;     // 0..2047
            int row = idx >> 8, rem = idx & 255;
            int qq = rem >> 4, x4 = rem & 15;
            int j = 8 * c + row;
            if (j > 62) j = 62;
            const float* src = Awb_blk + j * SP + (q0 + qq) * 64 + x4 * 4;
            uint32_t dst = As_u32 + (buf * AW_BUF + (row * 16 + qq) * 64 + x4 * 4) * 4;
            cp_async16(dst, src);
        }
    };

    stage(0, 0);
    cp_commit();

    ull z = packf2(0.0f, 0.0f);
    ull acc[8][4];
    #pragma unroll
    for (int m = 0; m < 8; ++m)
        #pragma unroll
        for (int cp = 0; cp < 4; ++cp) acc[m][cp] = z;

    const int thr = 8 * xo + 7;

    #pragma unroll 1
    for (int c = 0; c < 8; ++c) {
        if (c < 7) { stage(c + 1, (c + 1) & 1); cp_commit(); }
        if (c < 7) cp_wait<1>(); else cp_wait<0>();
        __syncthreads();

        const float* Ab = Aw_s + (c & 1) * AW_BUF;
        const int jmax = (c < 7) ? 8 : 7;

        #pragma unroll
        for (int jj = 0; jj < 8; ++jj) {
            if (jj >= jmax) break;
            const int j = 8 * c + jj;
            const float* ap = &Ab[(jj * 16 + qloc) * 64 + 8 * xo];
            float4 av0 = *(const float4*)ap;
            float4 av1 = *(const float4*)(ap + 4);

            int p = j + (j >= thr ? 1 : 0);
            const ull* u = reinterpret_cast<const ull*>(&pvw2[(qloc * 64 + p) * 18 + 4 * cg]);
            ull pp0 = u[0], pp1 = u[1], pp2 = u[2], pp3 = u[3];

            float a[8] = {av0.x, av0.y, av0.z, av0.w, av1.x, av1.y, av1.z, av1.w};
            #pragma unroll
            for (int m = 0; m < 8; ++m) {
                ull am = packf2(a[m], a[m]);
                ffma2(acc[m][0], am, pp0);
                ffma2(acc[m][1], am, pp1);
                ffma2(acc[m][2], am, pp2);
                ffma2(acc[m][3], am, pp3);
            }
        }
        __syncthreads();
    }

    // corrections: for j = 8xo+jj (jj 0..6), lanes m <= jj used pv[j] but need pv[j+1]
    #pragma unroll 1
    for (int jj = 0; jj < 7; ++jj) {
        int j = 8 * xo + jj;
        const ull* uj  = reinterpret_cast<const ull*>(&pvw2[(qloc * 64 + j) * 18 + 4 * cg]);
        const ull* uj1 = reinterpret_cast<const ull*>(&pvw2[(qloc * 64 + j + 1) * 18 + 4 * cg]);
        ull pj0 = uj[0], pj1 = uj[1], pj2 = uj[2], pj3 = uj[3];
        ull q0_ = uj1[0], q1_ = uj1[1], q2_ = uj1[2], q3_ = uj1[3];
        for (int m = 0; m <= jj; ++m) {
            float bb = __ldg(&Awb[j * SP + 8 * xo + m]);
            ull b2 = packf2(bb, bb);
            ull nb2 = packf2(-bb, -bb);
            ffma2(acc[m][0], b2, q0_); ffma2(acc[m][0], nb2, pj0);
            ffma2(acc[m][1], b2, q1_); ffma2(acc[m][1], nb2, pj1);
            ffma2(acc[m][2], b2, q2_); ffma2(acc[m][2], nb2, pj2);
            ffma2(acc[m][3], b2, q3_); ffma2(acc[m][3], nb2, pj3);
        }
    }

    // RMW store
    #pragma unroll
    for (int cp = 0; cp < 4; ++cp) {
        float lo[8], hi[8];
        #pragma unroll
        for (int m = 0; m < 8; ++m) unpackf2(acc[m][cp], lo[m], hi[m]);
        float* o0 = &out[(cbase + 8 * cg + 2 * cp) * SP + tau * PLANE + q * 64 + 8 * xo];
        float* o1 = o0 + SP;
        float4 a0 = *(float4*)o0;          float4 a1 = *(float4*)(o0 + 4);
        float4 b0v = *(float4*)o1;         float4 b1v = *(float4*)(o1 + 4);
        a0.x += lo[0]; a0.y += lo[1]; a0.z += lo[2]; a0.w += lo[3];
        a1.x += lo[4]; a1.y += lo[5]; a1.z += lo[6]; a1.w += lo[7];
        b0v.x += hi[0]; b0v.y += hi[1]; b0v.z += hi[2]; b0v.w += hi[3];
        b1v.x += hi[4]; b1v.y += hi[5]; b1v.z += hi[6]; b1v.w += hi[7];
        *(float4*)o0 = a0;       *(float4*)(o0 + 4) = a1;
        *(float4*)o1 = b0v;      *(float4*)(o1 + 4) = b1v;
    }
}

// ---------------------------------------------------------------------------

extern "C" void kernel_launch(void* const* d_in, const int* in_sizes, int n_in,
                              void* d_out, int out_size) {
    (void)in_sizes; (void)n_in; (void)out_size;
    const float* A    = (const float*)d_in[0];
    const float* V    = (const float*)d_in[1];
    const float* Wm   = (const float*)d_in[2];
    const float* bias = (const float*)d_in[3];
    float* out = (float*)d_out;

    const int SMEM_H = 32768 * 4 + 2 * AH_BUF * 4;   // 131072 + 92160 = 223232
    const int SMEM_W = 36864 * 4 + 2 * AW_BUF * 4;   // 147456 + 65536 = 212992

    cudaFuncSetAttribute(attn_h_kernel, cudaFuncAttributeMaxDynamicSharedMemorySize, SMEM_H);
    cudaFuncSetAttribute(attn_w_kernel, cudaFuncAttributeMaxDynamicSharedMemorySize, SMEM_W);

    conv_gemm_kernel<<<dim3(SP / 256, CDIM / 32), 256>>>(V, Wm, bias);
    attn_t_kernel<<<dim3(PLANE / 128, HEADS), 512>>>(A, out);
    attn_h_kernel<<<dim3(4, TT, HEADS), 512, SMEM_H>>>(A, out);
    attn_w_kernel<<<dim3(4, TT, HEADS), 512, SMEM_W>>>(A, out);
}